// round 10
// baseline (speedup 1.0000x reference)
#include <cuda_runtime.h>
#include <stdint.h>

// Ragged gather (verified wiring from R8 recon):
//   in0 = req_to_token [4096 x 32768] int32
//   in1 = req_pool_indices [64] int32
//   in2 = chunk_starts [64] int32
//   in3 = chunk_seq_lens [64] int32 (unused)
//   in4 = chunk_cu_seq_lens [65] int32
//   in5 = num_chunk_tokens [1] (== out_size)
// Output dtype is FLOAT32 (R8 conclusion: int32 writes bitcast to ~0 floats
// explain six rounds of rel_err == 1.000000 exactly).
//   out[t] = (float) req_to_token[pool[seg]*32768 + starts[seg] + (t - cu[seg])]
// R9 never ran (container failure) — resubmitting unchanged.

#define BMAX 64

__global__ __launch_bounds__(256)
void ragged_gather_kernel(
    const int* __restrict__ table,
    const int* __restrict__ pool,
    const int* __restrict__ starts,
    const int* __restrict__ cu,
    float* __restrict__ out,
    int T, int batch, int cols, int rows)
{
    __shared__ int s_cu[BMAX + 1];
    __shared__ int s_row[BMAX];
    __shared__ int s_start[BMAX];

    const int tid = threadIdx.x;
    if (tid <= batch) s_cu[tid] = cu[tid];
    if (tid < batch) {
        s_row[tid]   = pool[tid];
        s_start[tid] = starts[tid];
    }
    __syncthreads();

    const int t = blockIdx.x * blockDim.x + tid;
    if (t >= T) return;

    // Largest seg with s_cu[seg] <= t  (seg in [0, batch))
    int lo = 0, hi = batch - 1;
    while (lo < hi) {
        int mid = (lo + hi + 1) >> 1;
        if (s_cu[mid] <= t) lo = mid; else hi = mid - 1;
    }
    const int seg = lo;
    const int pos = t - s_cu[seg];

    int row = s_row[seg];
    int col = s_start[seg] + pos;
    // Cheap clamps: a fault would kill the launch; never triggered on valid data.
    if (row < 0) row = 0; else if (row >= rows) row = rows - 1;
    if (col < 0) col = 0; else if (col >= cols) col = cols - 1;

    out[t] = (float)table[(long long)row * cols + col];
}

extern "C" void kernel_launch(void* const* d_in, const int* in_sizes, int n_in,
                              void* d_out, int out_size)
{
    const int* table  = (const int*)d_in[0];
    const int* pool   = (const int*)d_in[1];
    const int* starts = (const int*)d_in[2];
    const int* cu     = (const int*)d_in[4];

    int batch = in_sizes[1];
    if (batch > BMAX) batch = BMAX;

    const int rows = 4096;                 // POOL_SIZE (verified: N = 4096*32768)
    const int cols = in_sizes[0] / rows;   // 32768

    const int T = out_size;
    if (T <= 0) return;

    const int threads = 256;
    const int blocks = (T + threads - 1) / threads;
    ragged_gather_kernel<<<blocks, threads>>>(
        table, pool, starts, cu, (float*)d_out, T, batch, cols, rows);
}